// round 6
// baseline (speedup 1.0000x reference)
#include <cuda_runtime.h>
#include <cuda_fp16.h>

#define W0 4096
#define OUTW 1024
#define MAXMIP 8

// Packed half4 texel: rgb + pad, 8 bytes.
struct __align__(8) h4 { __half2 rg; __half2 bz; };

// Mip chain levels 2..8 in fp16 texels. 1,398,016 texels * 8B = ~11.2MB.
// (Level 1 never materialized: lod<2 pixels compute it on the fly in fp32.)
__device__ h4 g_mh[1398016];
__device__ int g_done_count = 0;   // last-block counter (self-resetting)

// Texel offset of each level within g_mh (levels 0,1 handled from base).
__constant__ int MIPH_OFF[9] = {
    0, 0,
    0,          // level 2: 1024^2
    1048576,    // level 3:  512^2
    1310720,    // level 4:  256^2
    1376256,    // level 5:  128^2
    1392640,    // level 6:   64^2
    1396736,    // level 7:   32^2
    1397760     // level 8:   16^2
};

#define OFF_L2 0
#define OFF_L3 1048576
#define OFF_L4 1310720
#define OFF_L5 1376256
#define OFF_L6 1392640
#define OFF_L7 1396736
#define OFF_L8 1397760

__device__ __forceinline__ h4 pack_h4(float r, float g, float b) {
    h4 t;
    t.rg = __floats2half2_rn(r, g);
    t.bz = __floats2half2_rn(b, 0.0f);
    return t;
}

__device__ __forceinline__ float3 unpack_h4(h4 t) {
    float2 rg = __half22float2(t.rg);
    return make_float3(rg.x, rg.y, __low2float(t.bz));
}

__device__ __forceinline__ float3 f3avg(float3 a, float3 b, float3 c, float3 d) {
    return make_float3((a.x + b.x + c.x + d.x) * 0.25f,
                       (a.y + b.y + c.y + d.y) * 0.25f,
                       (a.z + b.z + c.z + d.z) * 0.25f);
}

__device__ __forceinline__ float4 f4avg4(float4 a, float4 b, float4 c, float4 d) {
    return make_float4((a.x + b.x + c.x + d.x) * 0.25f,
                       (a.y + b.y + c.y + d.y) * 0.25f,
                       (a.z + b.z + c.z + d.z) * 0.25f, 0.0f);
}

__device__ __forceinline__ void load12(float* r, const float4* p) {
    float4 f0 = p[0], f1 = p[1], f2 = p[2];
    r[0] = f0.x; r[1]  = f0.y; r[2]  = f0.z; r[3]  = f0.w;
    r[4] = f1.x; r[5]  = f1.y; r[6]  = f1.z; r[7]  = f1.w;
    r[8] = f2.x; r[9]  = f2.y; r[10] = f2.z; r[11] = f2.w;
}

// Kernel A: base (packed fp32 rgb) -> levels 2..6 (block-local smem reduction),
// then the LAST block produces L7, L8 from L6.
// Grid: (64,64) blocks of 256 threads; block = 16x16 L2 texels = one L6 texel.
__global__ __launch_bounds__(256) void vt_downA(const float* __restrict__ data) {
    __shared__ float4 s2[256];   // L3-input tile 16x16 (this block's L2 texels)
    __shared__ float4 s3[64];    // 8x8 L3
    __shared__ float4 s4[16];    // 4x4 L4
    __shared__ float4 s5[4];     // 2x2 L5
    __shared__ bool s_last;

    int t = threadIdx.x;
    int bx = blockIdx.x, by = blockIdx.y;
    int tx = t & 15, ty = t >> 4;

    int X2 = 16 * bx + tx;       // L2 coords (1024 wide)
    int Y2 = 16 * by + ty;

    // ---- base 4x4 -> one L2 texel ----
    {
        const int pitch4 = 3 * 1024;     // base row pitch in float4
        const float4* s = reinterpret_cast<const float4*>(data)
                          + (size_t)4 * Y2 * pitch4 + 3 * X2;
        float a[12], b[12];
        float3 l1[4];
#pragma unroll
        for (int half = 0; half < 2; half++) {
            load12(a, s + (2 * half) * pitch4);
            load12(b, s + (2 * half + 1) * pitch4);
#pragma unroll
            for (int dx = 0; dx < 2; dx++) {
                l1[2 * half + dx] = make_float3(
                    (a[6 * dx + 0] + a[6 * dx + 3] + b[6 * dx + 0] + b[6 * dx + 3]) * 0.25f,
                    (a[6 * dx + 1] + a[6 * dx + 4] + b[6 * dx + 1] + b[6 * dx + 4]) * 0.25f,
                    (a[6 * dx + 2] + a[6 * dx + 5] + b[6 * dx + 2] + b[6 * dx + 5]) * 0.25f);
            }
        }
        float3 l2 = f3avg(l1[0], l1[1], l1[2], l1[3]);
        g_mh[OFF_L2 + (size_t)Y2 * 1024 + X2] = pack_h4(l2.x, l2.y, l2.z);
        s2[ty * 16 + tx] = make_float4(l2.x, l2.y, l2.z, 0.0f);
    }
    __syncthreads();

    // ---- L3 (8x8 per block) ----
    if (t < 64) {
        int x = t & 7, y = t >> 3;
        float4 v = f4avg4(s2[(2 * y) * 16 + 2 * x],     s2[(2 * y) * 16 + 2 * x + 1],
                          s2[(2 * y + 1) * 16 + 2 * x], s2[(2 * y + 1) * 16 + 2 * x + 1]);
        g_mh[OFF_L3 + (size_t)(8 * by + y) * 512 + (8 * bx + x)] = pack_h4(v.x, v.y, v.z);
        s3[y * 8 + x] = v;
    }
    __syncthreads();

    // ---- L4 (4x4) ----
    if (t < 16) {
        int x = t & 3, y = t >> 2;
        float4 v = f4avg4(s3[(2 * y) * 8 + 2 * x],     s3[(2 * y) * 8 + 2 * x + 1],
                          s3[(2 * y + 1) * 8 + 2 * x], s3[(2 * y + 1) * 8 + 2 * x + 1]);
        g_mh[OFF_L4 + (size_t)(4 * by + y) * 256 + (4 * bx + x)] = pack_h4(v.x, v.y, v.z);
        s4[y * 4 + x] = v;
    }
    __syncthreads();

    // ---- L5 (2x2) ----
    if (t < 4) {
        int x = t & 1, y = t >> 1;
        float4 v = f4avg4(s4[(2 * y) * 4 + 2 * x],     s4[(2 * y) * 4 + 2 * x + 1],
                          s4[(2 * y + 1) * 4 + 2 * x], s4[(2 * y + 1) * 4 + 2 * x + 1]);
        g_mh[OFF_L5 + (size_t)(2 * by + y) * 128 + (2 * bx + x)] = pack_h4(v.x, v.y, v.z);
        s5[y * 2 + x] = v;
    }
    __syncthreads();

    // ---- L6 (1 per block) ----
    if (t == 0) {
        float4 v = f4avg4(s5[0], s5[1], s5[2], s5[3]);
        g_mh[OFF_L6 + (size_t)by * 64 + bx] = pack_h4(v.x, v.y, v.z);
    }

    // ---- last-block: L6 -> L7, L8 ----
    if (t == 0) {
        __threadfence();
        int prev = atomicAdd(&g_done_count, 1);
        s_last = (prev == 64 * 64 - 1);
    }
    __syncthreads();

    if (s_last) {
        __threadfence();   // acquire: make other blocks' L6 writes visible
        // 256 threads; thread t -> one L8 texel (16x16) from a 4x4 L6 region,
        // emitting 2x2 L7 texels on the way.
        int x8 = t & 15, y8 = t >> 4;
        const h4* L6p = g_mh + OFF_L6;
        float3 r[4][4];
#pragma unroll
        for (int dy = 0; dy < 4; dy++)
#pragma unroll
            for (int dx = 0; dx < 4; dx++)
                r[dy][dx] = unpack_h4(L6p[(size_t)(4 * y8 + dy) * 64 + (4 * x8 + dx)]);

        float3 l7[4];
#pragma unroll
        for (int dy = 0; dy < 2; dy++)
#pragma unroll
            for (int dx = 0; dx < 2; dx++) {
                l7[2 * dy + dx] = f3avg(r[2 * dy][2 * dx], r[2 * dy][2 * dx + 1],
                                        r[2 * dy + 1][2 * dx], r[2 * dy + 1][2 * dx + 1]);
                g_mh[OFF_L7 + (size_t)(2 * y8 + dy) * 32 + (2 * x8 + dx)] =
                    pack_h4(l7[2 * dy + dx].x, l7[2 * dy + dx].y, l7[2 * dy + dx].z);
            }

        float3 l8 = f3avg(l7[0], l7[1], l7[2], l7[3]);
        g_mh[OFF_L8 + (size_t)y8 * 16 + x8] = pack_h4(l8.x, l8.y, l8.z);

        if (t == 0) g_done_count = 0;   // reset for next graph replay
    }
}

// wrap helpers
__device__ __forceinline__ void wrap_setup(float u, float v, int w,
                                           int& x0, int& y0, int& x1, int& y1,
                                           float& fx, float& fy) {
    float x = u * (float)w - 0.5f;
    float y = v * (float)w - 0.5f;
    float x0f = floorf(x);
    float y0f = floorf(y);
    fx = x - x0f;
    fy = y - y0f;
    x0 = (int)x0f;
    y0 = (int)y0f;
    if (x0 < 0) x0 += w;
    if (y0 < 0) y0 += w;
    x1 = x0 + 1; if (x1 == w) x1 = 0;
    y1 = y0 + 1; if (y1 == w) y1 = 0;
}

// Bilinear fetch (wrap) from fp16 mip storage (levels >= 2). One 8B load per tap.
__device__ __forceinline__ void vt_bilinear_h(const h4* __restrict__ tex, int w,
                                              float u, float v, float rgb[3]) {
    int x0, y0, x1, y1; float fx, fy;
    wrap_setup(u, v, w, x0, y0, x1, y1, fx, fy);

    float3 p00 = unpack_h4(tex[(size_t)y0 * w + x0]);
    float3 p01 = unpack_h4(tex[(size_t)y0 * w + x1]);
    float3 p10 = unpack_h4(tex[(size_t)y1 * w + x0]);
    float3 p11 = unpack_h4(tex[(size_t)y1 * w + x1]);

    float w00 = (1.0f - fx) * (1.0f - fy);
    float w01 = fx * (1.0f - fy);
    float w10 = (1.0f - fx) * fy;
    float w11 = fx * fy;

    rgb[0] = p00.x * w00 + p01.x * w01 + p10.x * w10 + p11.x * w11;
    rgb[1] = p00.y * w00 + p01.y * w01 + p10.y * w10 + p11.y * w11;
    rgb[2] = p00.z * w00 + p01.z * w01 + p10.z * w10 + p11.z * w11;
}

// Exact fp32 bilinear on the base texture (level 0). float2-vectorized.
__device__ __forceinline__ void vt_bilinear0(const float* __restrict__ tex,
                                             float u, float v, float rgb[3]) {
    int x0, y0, x1, y1; float fx, fy;
    wrap_setup(u, v, W0, x0, y0, x1, y1, fx, fy);

    const float* p00 = tex + ((size_t)y0 * W0 + x0) * 3;
    const float* p01 = tex + ((size_t)y0 * W0 + x1) * 3;
    const float* p10 = tex + ((size_t)y1 * W0 + x0) * 3;
    const float* p11 = tex + ((size_t)y1 * W0 + x1) * 3;

    float w00 = (1.0f - fx) * (1.0f - fy);
    float w01 = fx * (1.0f - fy);
    float w10 = (1.0f - fx) * fy;
    float w11 = fx * fy;

#pragma unroll
    for (int c = 0; c < 3; c++)
        rgb[c] = p00[c] * w00 + p01[c] * w01 + p10[c] * w10 + p11[c] * w11;
}

// On-the-fly L1 texel (lx,ly) in exact fp32: avg of base 2x2. float2 loads.
__device__ __forceinline__ float3 l1_texel(const float* __restrict__ base,
                                           int lx, int ly) {
    const float2* r0 = reinterpret_cast<const float2*>(
        base + ((size_t)(2 * ly) * W0 + 2 * lx) * 3);
    const float2* r1 = reinterpret_cast<const float2*>(
        base + ((size_t)(2 * ly + 1) * W0 + 2 * lx) * 3);
    float2 a0 = r0[0], a1 = r0[1], a2 = r0[2];
    float2 b0 = r1[0], b1 = r1[1], b2 = r1[2];
    // texel0 rgb = (a0.x,a0.y,a1.x); texel1 rgb = (a1.y,a2.x,a2.y)
    return make_float3((a0.x + a1.y + b0.x + b1.y) * 0.25f,
                       (a0.y + a2.x + b0.y + b2.x) * 0.25f,
                       (a1.x + a2.y + b1.x + b2.y) * 0.25f);
}

// Exact fp32 bilinear at level 1, L1 texels computed on the fly.
__device__ __forceinline__ void vt_bilinear_l1(const float* __restrict__ tex,
                                               float u, float v, float rgb[3]) {
    const int w1 = W0 >> 1;   // 2048
    int x0, y0, x1, y1; float fx, fy;
    wrap_setup(u, v, w1, x0, y0, x1, y1, fx, fy);

    float3 t00 = l1_texel(tex, x0, y0);
    float3 t01 = l1_texel(tex, x1, y0);
    float3 t10 = l1_texel(tex, x0, y1);
    float3 t11 = l1_texel(tex, x1, y1);

    float w00 = (1.0f - fx) * (1.0f - fy);
    float w01 = fx * (1.0f - fy);
    float w10 = (1.0f - fx) * fy;
    float w11 = fx * fy;

    rgb[0] = t00.x * w00 + t01.x * w01 + t10.x * w10 + t11.x * w11;
    rgb[1] = t00.y * w00 + t01.y * w01 + t10.y * w10 + t11.y * w11;
    rgb[2] = t00.z * w00 + t01.z * w01 + t10.z * w10 + t11.z * w11;
}

__global__ __launch_bounds__(256) void vt_sample(const float* __restrict__ data,
                          const float2* __restrict__ texc,
                          const float4* __restrict__ deriv,
                          float* __restrict__ out) {
    int i = blockIdx.x * blockDim.x + threadIdx.x;
    if (i >= OUTW * OUTW) return;

    float2 uv = texc[i];
    float4 d = deriv[i];

    float dudx = d.x * (float)W0;
    float dvdx = d.y * (float)W0;
    float dudy = d.z * (float)W0;
    float dvdy = d.w * (float)W0;

    float rho2 = fmaxf(dudx * dudx + dvdx * dvdx, dudy * dudy + dvdy * dvdy);
    float lod = 0.5f * __log2f(fmaxf(rho2, 1e-20f));
    lod = fminf(fmaxf(lod, 0.0f), (float)MAXMIP);

    int l0 = (int)lod;
    if (l0 > MAXMIP) l0 = MAXMIP;
    float frac = lod - (float)l0;
    int l1 = (l0 < MAXMIP) ? (l0 + 1) : MAXMIP;

    float a[3], b[3];
    if (l0 >= 2) {
        // common path (~98.7% of pixels)
        vt_bilinear_h(g_mh + MIPH_OFF[l0], W0 >> l0, uv.x, uv.y, a);
        vt_bilinear_h(g_mh + MIPH_OFF[l1], W0 >> l1, uv.x, uv.y, b);
    } else if (l0 == 1) {
        vt_bilinear_l1(data, uv.x, uv.y, a);
        vt_bilinear_h(g_mh + OFF_L2, W0 >> 2, uv.x, uv.y, b);
    } else {
        vt_bilinear0(data, uv.x, uv.y, a);
        vt_bilinear_l1(data, uv.x, uv.y, b);
    }

    float w0 = 1.0f - frac;
    out[(size_t)3 * i + 0] = a[0] * w0 + b[0] * frac;
    out[(size_t)3 * i + 1] = a[1] * w0 + b[1] * frac;
    out[(size_t)3 * i + 2] = a[2] * w0 + b[2] * frac;
}

extern "C" void kernel_launch(void* const* d_in, const int* in_sizes, int n_in,
                              void* d_out, int out_size) {
    const float* data  = (const float*)d_in[0];   // [1,4096,4096,3]
    const float2* texc = (const float2*)d_in[1];  // [1,1024,1024,2]
    const float4* deriv = (const float4*)d_in[2]; // [1,1024,1024,4]
    float* out = (float*)d_out;                   // [1,1024,1024,3]

    (void)in_sizes; (void)n_in; (void)out_size;

    // A: base -> L2..L8 (single kernel, last-block finishes L7/L8)
    {
        dim3 grid(64, 64);
        vt_downA<<<grid, 256>>>(data);
    }
    // Trilinear sample
    vt_sample<<<4096, 256>>>(data, texc, deriv, out);
}

// round 7
// speedup vs baseline: 1.0691x; 1.0691x over previous
#include <cuda_runtime.h>
#include <cuda_fp16.h>

#define W0 4096
#define OUTW 1024
#define MAXMIP 8

// Packed half4 texel: rgb + pad, 8 bytes.
struct __align__(8) h4 { __half2 rg; __half2 bz; };
// Paired entry: {texel(x), texel((x+1) mod w)} -> one 16B load covers a bilinear row.
struct __align__(16) hp { h4 lo; h4 hi; };

// Mip chain levels 2..8, paired entries. 1,398,016 entries * 16B = ~22.4MB.
// (Level 1 never materialized: lod<2 pixels compute it on the fly in fp32.)
__device__ hp g_mh[1398016];

// Entry offset of each level within g_mh (entry index == texel index).
__constant__ int MIPH_OFF[9] = {
    0, 0,
    0,          // level 2: 1024^2
    1048576,    // level 3:  512^2
    1310720,    // level 4:  256^2
    1376256,    // level 5:  128^2
    1392640,    // level 6:   64^2
    1396736,    // level 7:   32^2
    1397760     // level 8:   16^2
};

#define OFF_L2 0
#define OFF_L3 1048576
#define OFF_L4 1310720
#define OFF_L5 1376256
#define OFF_L6 1392640
#define OFF_L7 1396736
#define OFF_L8 1397760

__device__ __forceinline__ h4 pack_h4(float r, float g, float b) {
    h4 t;
    t.rg = __floats2half2_rn(r, g);
    t.bz = __floats2half2_rn(b, 0.0f);
    return t;
}

// Write texel (x,y) of a w-wide level into both pair slots that reference it:
// lo slot of entry x, hi slot of entry (x-1) mod w. w must be a power of two.
__device__ __forceinline__ void store_pair(hp* __restrict__ base, int w,
                                           int x, int y, float3 v) {
    h4 t = pack_h4(v.x, v.y, v.z);
    uint2 u = *reinterpret_cast<uint2*>(&t);
    *reinterpret_cast<uint2*>(&base[(size_t)y * w + x].lo) = u;
    *reinterpret_cast<uint2*>(&base[(size_t)y * w + ((x - 1) & (w - 1))].hi) = u;
}

__device__ __forceinline__ float3 f3avg(float3 a, float3 b, float3 c, float3 d) {
    return make_float3((a.x + b.x + c.x + d.x) * 0.25f,
                       (a.y + b.y + c.y + d.y) * 0.25f,
                       (a.z + b.z + c.z + d.z) * 0.25f);
}

__device__ __forceinline__ float4 f4avg4(float4 a, float4 b, float4 c, float4 d) {
    return make_float4((a.x + b.x + c.x + d.x) * 0.25f,
                       (a.y + b.y + c.y + d.y) * 0.25f,
                       (a.z + b.z + c.z + d.z) * 0.25f, 0.0f);
}

__device__ __forceinline__ void load12(float* r, const float4* p) {
    float4 f0 = p[0], f1 = p[1], f2 = p[2];
    r[0] = f0.x; r[1]  = f0.y; r[2]  = f0.z; r[3]  = f0.w;
    r[4] = f1.x; r[5]  = f1.y; r[6]  = f1.z; r[7]  = f1.w;
    r[8] = f2.x; r[9]  = f2.y; r[10] = f2.z; r[11] = f2.w;
}

// Kernel A: base (packed fp32 rgb) -> level 2 only (paired writes).
// One thread = one L2 texel = 4x4 base texels.
__global__ __launch_bounds__(256) void vt_downA(const float* __restrict__ data) {
    const int w2 = W0 >> 2;              // 1024
    int i = blockIdx.x * blockDim.x + threadIdx.x;
    if (i >= w2 * w2) return;

    int x2 = i & (w2 - 1);
    int y2 = i >> 10;
    const int pitch4 = 3 * w2;           // base row pitch in float4
    const float4* s4 = reinterpret_cast<const float4*>(data)
                       + (size_t)4 * y2 * pitch4 + 3 * x2;

    float a[12], b[12];
    float3 l1[4];

#pragma unroll
    for (int half = 0; half < 2; half++) {
        load12(a, s4 + (2 * half) * pitch4);
        load12(b, s4 + (2 * half + 1) * pitch4);
#pragma unroll
        for (int dx = 0; dx < 2; dx++) {
            l1[2 * half + dx] = make_float3(
                (a[6 * dx + 0] + a[6 * dx + 3] + b[6 * dx + 0] + b[6 * dx + 3]) * 0.25f,
                (a[6 * dx + 1] + a[6 * dx + 4] + b[6 * dx + 1] + b[6 * dx + 4]) * 0.25f,
                (a[6 * dx + 2] + a[6 * dx + 5] + b[6 * dx + 2] + b[6 * dx + 5]) * 0.25f);
        }
    }

    float3 l2 = f3avg(l1[0], l1[1], l1[2], l1[3]);
    store_pair(g_mh + OFF_L2, 1024, x2, y2, l2);
}

__device__ __forceinline__ float3 pair_lo(uint4 e) {
    __half2 rg = *reinterpret_cast<__half2*>(&e.x);
    __half2 bz = *reinterpret_cast<__half2*>(&e.y);
    float2 f = __half22float2(rg);
    return make_float3(f.x, f.y, __low2float(bz));
}
__device__ __forceinline__ float3 pair_hi(uint4 e) {
    __half2 rg = *reinterpret_cast<__half2*>(&e.z);
    __half2 bz = *reinterpret_cast<__half2*>(&e.w);
    float2 f = __half22float2(rg);
    return make_float3(f.x, f.y, __low2float(bz));
}

// Kernel B: level 2 -> levels 3..8 in one kernel.
// Block = 64x64 L2 tile (one L8 texel). Grid: 16x16 blocks of 256 threads.
__global__ __launch_bounds__(256) void vt_downB() {
    __shared__ float4 s4[256];   // L4 tile 16x16
    __shared__ float4 s5[64];    // L5 tile 8x8
    __shared__ float4 s6[16];    // L6 tile 4x4
    __shared__ float4 s7[4];     // L7 tile 2x2

    const hp* __restrict__ L2t = g_mh + OFF_L2;
    hp* __restrict__ L3 = g_mh + OFF_L3;
    hp* __restrict__ L4 = g_mh + OFF_L4;
    hp* __restrict__ L5 = g_mh + OFF_L5;
    hp* __restrict__ L6 = g_mh + OFF_L6;
    hp* __restrict__ L7 = g_mh + OFF_L7;
    hp* __restrict__ L8 = g_mh + OFF_L8;

    int t = threadIdx.x;
    int bx = blockIdx.x, by = blockIdx.y;
    int tx = t & 15, ty = t >> 4;

    // Each thread: 4x4 L2 texels at (64bx + 4tx, 64by + 4ty).
    // Entries x0 and x0+2 give texels x0..x0+3 (x0 even).
    {
        int x0 = 64 * bx + 4 * tx;
        int y0 = 64 * by + 4 * ty;
        const uint4* src = reinterpret_cast<const uint4*>(L2t + (size_t)y0 * 1024 + x0);

        float3 r[4][4];
#pragma unroll
        for (int dy = 0; dy < 4; dy++) {
            uint4 q0 = src[(size_t)dy * 1024];
            uint4 q1 = src[(size_t)dy * 1024 + 2];
            r[dy][0] = pair_lo(q0);
            r[dy][1] = pair_hi(q0);
            r[dy][2] = pair_lo(q1);
            r[dy][3] = pair_hi(q1);
        }

        float3 l3[4];
#pragma unroll
        for (int dy = 0; dy < 2; dy++)
#pragma unroll
            for (int dx = 0; dx < 2; dx++)
                l3[2 * dy + dx] = f3avg(r[2 * dy][2 * dx], r[2 * dy][2 * dx + 1],
                                        r[2 * dy + 1][2 * dx], r[2 * dy + 1][2 * dx + 1]);

        int x3 = 32 * bx + 2 * tx;
        int y3 = 32 * by + 2 * ty;
        store_pair(L3, 512, x3,     y3,     l3[0]);
        store_pair(L3, 512, x3 + 1, y3,     l3[1]);
        store_pair(L3, 512, x3,     y3 + 1, l3[2]);
        store_pair(L3, 512, x3 + 1, y3 + 1, l3[3]);

        float3 l4 = f3avg(l3[0], l3[1], l3[2], l3[3]);
        store_pair(L4, 256, 16 * bx + tx, 16 * by + ty, l4);
        s4[ty * 16 + tx] = make_float4(l4.x, l4.y, l4.z, 0.0f);
    }
    __syncthreads();

    if (t < 64) {
        int x = t & 7, y = t >> 3;
        float4 v = f4avg4(s4[(2 * y) * 16 + 2 * x],     s4[(2 * y) * 16 + 2 * x + 1],
                          s4[(2 * y + 1) * 16 + 2 * x], s4[(2 * y + 1) * 16 + 2 * x + 1]);
        store_pair(L5, 128, 8 * bx + x, 8 * by + y, make_float3(v.x, v.y, v.z));
        s5[y * 8 + x] = v;
    }
    __syncthreads();

    if (t < 16) {
        int x = t & 3, y = t >> 2;
        float4 v = f4avg4(s5[(2 * y) * 8 + 2 * x],     s5[(2 * y) * 8 + 2 * x + 1],
                          s5[(2 * y + 1) * 8 + 2 * x], s5[(2 * y + 1) * 8 + 2 * x + 1]);
        store_pair(L6, 64, 4 * bx + x, 4 * by + y, make_float3(v.x, v.y, v.z));
        s6[y * 4 + x] = v;
    }
    __syncthreads();

    if (t < 4) {
        int x = t & 1, y = t >> 1;
        float4 v = f4avg4(s6[(2 * y) * 4 + 2 * x],     s6[(2 * y) * 4 + 2 * x + 1],
                          s6[(2 * y + 1) * 4 + 2 * x], s6[(2 * y + 1) * 4 + 2 * x + 1]);
        store_pair(L7, 32, 2 * bx + x, 2 * by + y, make_float3(v.x, v.y, v.z));
        s7[y * 2 + x] = v;
    }
    __syncthreads();

    if (t == 0) {
        float4 a = s7[0], b = s7[1], c = s7[2], d = s7[3];
        store_pair(L8, 16, bx, by,
                   make_float3((a.x + b.x + c.x + d.x) * 0.25f,
                               (a.y + b.y + c.y + d.y) * 0.25f,
                               (a.z + b.z + c.z + d.z) * 0.25f));
    }
}

// wrap helpers
__device__ __forceinline__ void wrap_setup(float u, float v, int w,
                                           int& x0, int& y0, int& x1, int& y1,
                                           float& fx, float& fy) {
    float x = u * (float)w - 0.5f;
    float y = v * (float)w - 0.5f;
    float x0f = floorf(x);
    float y0f = floorf(y);
    fx = x - x0f;
    fy = y - y0f;
    x0 = (int)x0f;
    y0 = (int)y0f;
    if (x0 < 0) x0 += w;
    if (y0 < 0) y0 += w;
    x1 = x0 + 1; if (x1 == w) x1 = 0;
    y1 = y0 + 1; if (y1 == w) y1 = 0;
}

// Bilinear fetch (wrap) from paired fp16 mip storage: 2 x LDG.128 total.
__device__ __forceinline__ void vt_bilinear_h(const hp* __restrict__ tex, int w,
                                              float u, float v, float rgb[3]) {
    int x0, y0, x1, y1; float fx, fy;
    wrap_setup(u, v, w, x0, y0, x1, y1, fx, fy);

    uint4 e0 = *reinterpret_cast<const uint4*>(&tex[(size_t)y0 * w + x0]);
    uint4 e1 = *reinterpret_cast<const uint4*>(&tex[(size_t)y1 * w + x0]);

    float3 t00 = pair_lo(e0), t01 = pair_hi(e0);
    float3 t10 = pair_lo(e1), t11 = pair_hi(e1);

    float w00 = (1.0f - fx) * (1.0f - fy);
    float w01 = fx * (1.0f - fy);
    float w10 = (1.0f - fx) * fy;
    float w11 = fx * fy;

    rgb[0] = t00.x * w00 + t01.x * w01 + t10.x * w10 + t11.x * w11;
    rgb[1] = t00.y * w00 + t01.y * w01 + t10.y * w10 + t11.y * w11;
    rgb[2] = t00.z * w00 + t01.z * w01 + t10.z * w10 + t11.z * w11;
}

// Exact fp32 bilinear on the base texture (level 0). Rare path.
__device__ __forceinline__ void vt_bilinear0(const float* __restrict__ tex,
                                             float u, float v, float rgb[3]) {
    int x0, y0, x1, y1; float fx, fy;
    wrap_setup(u, v, W0, x0, y0, x1, y1, fx, fy);

    const float* p00 = tex + ((size_t)y0 * W0 + x0) * 3;
    const float* p01 = tex + ((size_t)y0 * W0 + x1) * 3;
    const float* p10 = tex + ((size_t)y1 * W0 + x0) * 3;
    const float* p11 = tex + ((size_t)y1 * W0 + x1) * 3;

    float w00 = (1.0f - fx) * (1.0f - fy);
    float w01 = fx * (1.0f - fy);
    float w10 = (1.0f - fx) * fy;
    float w11 = fx * fy;

#pragma unroll
    for (int c = 0; c < 3; c++)
        rgb[c] = p00[c] * w00 + p01[c] * w01 + p10[c] * w10 + p11[c] * w11;
}

// On-the-fly L1 texel (lx,ly) in exact fp32: avg of base 2x2. float2 loads.
__device__ __forceinline__ float3 l1_texel(const float* __restrict__ base,
                                           int lx, int ly) {
    const float2* r0 = reinterpret_cast<const float2*>(
        base + ((size_t)(2 * ly) * W0 + 2 * lx) * 3);
    const float2* r1 = reinterpret_cast<const float2*>(
        base + ((size_t)(2 * ly + 1) * W0 + 2 * lx) * 3);
    float2 a0 = r0[0], a1 = r0[1], a2 = r0[2];
    float2 b0 = r1[0], b1 = r1[1], b2 = r1[2];
    return make_float3((a0.x + a1.y + b0.x + b1.y) * 0.25f,
                       (a0.y + a2.x + b0.y + b2.x) * 0.25f,
                       (a1.x + a2.y + b1.x + b2.y) * 0.25f);
}

// Exact fp32 bilinear at level 1, L1 texels computed on the fly. Rare path.
__device__ __forceinline__ void vt_bilinear_l1(const float* __restrict__ tex,
                                               float u, float v, float rgb[3]) {
    const int w1 = W0 >> 1;   // 2048
    int x0, y0, x1, y1; float fx, fy;
    wrap_setup(u, v, w1, x0, y0, x1, y1, fx, fy);

    float3 t00 = l1_texel(tex, x0, y0);
    float3 t01 = l1_texel(tex, x1, y0);
    float3 t10 = l1_texel(tex, x0, y1);
    float3 t11 = l1_texel(tex, x1, y1);

    float w00 = (1.0f - fx) * (1.0f - fy);
    float w01 = fx * (1.0f - fy);
    float w10 = (1.0f - fx) * fy;
    float w11 = fx * fy;

    rgb[0] = t00.x * w00 + t01.x * w01 + t10.x * w10 + t11.x * w11;
    rgb[1] = t00.y * w00 + t01.y * w01 + t10.y * w10 + t11.y * w11;
    rgb[2] = t00.z * w00 + t01.z * w01 + t10.z * w10 + t11.z * w11;
}

__device__ __forceinline__ void sample_one(const float* __restrict__ data,
                                           float u, float v, float4 d,
                                           float rgb[3]) {
    float dudx = d.x * (float)W0;
    float dvdx = d.y * (float)W0;
    float dudy = d.z * (float)W0;
    float dvdy = d.w * (float)W0;

    float rho2 = fmaxf(dudx * dudx + dvdx * dvdx, dudy * dudy + dvdy * dvdy);
    float lod = 0.5f * __log2f(fmaxf(rho2, 1e-20f));
    lod = fminf(fmaxf(lod, 0.0f), (float)MAXMIP);

    int l0 = (int)lod;
    if (l0 > MAXMIP) l0 = MAXMIP;
    float frac = lod - (float)l0;
    int l1 = (l0 < MAXMIP) ? (l0 + 1) : MAXMIP;

    float a[3], b[3];
    if (l0 >= 2) {
        // common path (~98.7% of pixels)
        vt_bilinear_h(g_mh + MIPH_OFF[l0], W0 >> l0, u, v, a);
        vt_bilinear_h(g_mh + MIPH_OFF[l1], W0 >> l1, u, v, b);
    } else if (l0 == 1) {
        vt_bilinear_l1(data, u, v, a);
        vt_bilinear_h(g_mh + OFF_L2, W0 >> 2, u, v, b);
    } else {
        vt_bilinear0(data, u, v, a);
        vt_bilinear_l1(data, u, v, b);
    }

    float w0 = 1.0f - frac;
    rgb[0] = a[0] * w0 + b[0] * frac;
    rgb[1] = a[1] * w0 + b[1] * frac;
    rgb[2] = a[2] * w0 + b[2] * frac;
}

// Two pixels per thread: doubled MLP on the gather path, coalesced IO.
__global__ __launch_bounds__(256) void vt_sample(const float* __restrict__ data,
                          const float4* __restrict__ texc2,
                          const float4* __restrict__ deriv,
                          float* __restrict__ out) {
    int p = blockIdx.x * blockDim.x + threadIdx.x;
    const int npairs = OUTW * OUTW / 2;
    if (p >= npairs) return;

    float4 uvs = texc2[p];                 // (u0,v0,u1,v1)
    float4 d0 = deriv[2 * p];
    float4 d1 = deriv[2 * p + 1];

    float r0[3], r1[3];
    sample_one(data, uvs.x, uvs.y, d0, r0);
    sample_one(data, uvs.z, uvs.w, d1, r1);

    float2* o = reinterpret_cast<float2*>(out + (size_t)6 * p);
    o[0] = make_float2(r0[0], r0[1]);
    o[1] = make_float2(r0[2], r1[0]);
    o[2] = make_float2(r1[1], r1[2]);
}

extern "C" void kernel_launch(void* const* d_in, const int* in_sizes, int n_in,
                              void* d_out, int out_size) {
    const float* data  = (const float*)d_in[0];   // [1,4096,4096,3]
    const float4* texc2 = (const float4*)d_in[1]; // [1,1024,1024,2] read as pairs
    const float4* deriv = (const float4*)d_in[2]; // [1,1024,1024,4]
    float* out = (float*)d_out;                   // [1,1024,1024,3]

    (void)in_sizes; (void)n_in; (void)out_size;

    // A: base -> L2
    vt_downA<<<4096, 256>>>(data);
    // B: L2 -> L3..L8
    {
        dim3 grid(16, 16);
        vt_downB<<<grid, 256>>>();
    }
    // Trilinear sample (2 px/thread)
    vt_sample<<<2048, 256>>>(data, texc2, deriv, out);
}

// round 8
// speedup vs baseline: 1.1184x; 1.0461x over previous
#include <cuda_runtime.h>

#define W0 4096
#define OUTW 1024
#define MAXMIP 8

// Mip texel = 4B fixed point: r[0:11) g[11:22) b[22:32)  (values in [0,1]).
// Quad entry (16B, uint4): texels {(x,y),(x+1,y),(x,y+1),(x+1,y+1)} with wrap.
// Levels 2..8: 1,398,016 entries * 16B = ~22.4MB.
__device__ uint4 g_mq[1398016];

// Entry offset of each level within g_mq (entry index == texel index).
__constant__ int MIPQ_OFF[9] = {
    0, 0,
    0,          // level 2: 1024^2
    1048576,    // level 3:  512^2
    1310720,    // level 4:  256^2
    1376256,    // level 5:  128^2
    1392640,    // level 6:   64^2
    1396736,    // level 7:   32^2
    1397760     // level 8:   16^2
};

#define OFF_L2 0
#define OFF_L3 1048576
#define OFF_L4 1310720
#define OFF_L5 1376256
#define OFF_L6 1392640
#define OFF_L7 1396736
#define OFF_L8 1397760

__device__ __forceinline__ unsigned pack_rgb(float3 v) {
    unsigned r = (unsigned)__float2int_rn(__saturatef(v.x) * 2047.0f);
    unsigned g = (unsigned)__float2int_rn(__saturatef(v.y) * 2047.0f);
    unsigned b = (unsigned)__float2int_rn(__saturatef(v.z) * 1023.0f);
    return r | (g << 11) | (b << 22);
}

__device__ __forceinline__ float3 unpack_rgb(unsigned p) {
    return make_float3((float)(p & 2047u) * (1.0f / 2047.0f),
                       (float)((p >> 11) & 2047u) * (1.0f / 2047.0f),
                       (float)(p >> 22) * (1.0f / 1023.0f));
}

// Write texel (x,y) into the 4 quad entries that reference it (w = power of 2).
__device__ __forceinline__ void store_quad(unsigned* __restrict__ base, int w,
                                           int x, int y, float3 v) {
    unsigned p = pack_rgb(v);
    int xm = (x - 1) & (w - 1);
    int ym = (y - 1) & (w - 1);
    base[((size_t)y * w + x) * 4 + 0] = p;
    base[((size_t)y * w + xm) * 4 + 1] = p;
    base[((size_t)ym * w + x) * 4 + 2] = p;
    base[((size_t)ym * w + xm) * 4 + 3] = p;
}

__device__ __forceinline__ float3 f3avg(float3 a, float3 b, float3 c, float3 d) {
    return make_float3((a.x + b.x + c.x + d.x) * 0.25f,
                       (a.y + b.y + c.y + d.y) * 0.25f,
                       (a.z + b.z + c.z + d.z) * 0.25f);
}

// Average the 4 texels of a quad entry.
__device__ __forceinline__ float3 quad_avg(uint4 q) {
    return f3avg(unpack_rgb(q.x), unpack_rgb(q.y), unpack_rgb(q.z), unpack_rgb(q.w));
}

__device__ __forceinline__ float4 f4avg4(float4 a, float4 b, float4 c, float4 d) {
    return make_float4((a.x + b.x + c.x + d.x) * 0.25f,
                       (a.y + b.y + c.y + d.y) * 0.25f,
                       (a.z + b.z + c.z + d.z) * 0.25f, 0.0f);
}

__device__ __forceinline__ void load12(float* r, const float4* p) {
    float4 f0 = p[0], f1 = p[1], f2 = p[2];
    r[0] = f0.x; r[1]  = f0.y; r[2]  = f0.z; r[3]  = f0.w;
    r[4] = f1.x; r[5]  = f1.y; r[6]  = f1.z; r[7]  = f1.w;
    r[8] = f2.x; r[9]  = f2.y; r[10] = f2.z; r[11] = f2.w;
}

// Kernel A: base (packed fp32 rgb) -> level 2 only (quad writes).
// One thread = one L2 texel = 4x4 base texels.
__global__ __launch_bounds__(256) void vt_downA(const float* __restrict__ data) {
    const int w2 = W0 >> 2;              // 1024
    int i = blockIdx.x * blockDim.x + threadIdx.x;
    if (i >= w2 * w2) return;

    int x2 = i & (w2 - 1);
    int y2 = i >> 10;
    const int pitch4 = 3 * w2;           // base row pitch in float4
    const float4* s4 = reinterpret_cast<const float4*>(data)
                       + (size_t)4 * y2 * pitch4 + 3 * x2;

    float a[12], b[12];
    float3 l1[4];

#pragma unroll
    for (int half = 0; half < 2; half++) {
        load12(a, s4 + (2 * half) * pitch4);
        load12(b, s4 + (2 * half + 1) * pitch4);
#pragma unroll
        for (int dx = 0; dx < 2; dx++) {
            l1[2 * half + dx] = make_float3(
                (a[6 * dx + 0] + a[6 * dx + 3] + b[6 * dx + 0] + b[6 * dx + 3]) * 0.25f,
                (a[6 * dx + 1] + a[6 * dx + 4] + b[6 * dx + 1] + b[6 * dx + 4]) * 0.25f,
                (a[6 * dx + 2] + a[6 * dx + 5] + b[6 * dx + 2] + b[6 * dx + 5]) * 0.25f);
        }
    }

    float3 l2 = f3avg(l1[0], l1[1], l1[2], l1[3]);
    store_quad(reinterpret_cast<unsigned*>(g_mq + OFF_L2), 1024, x2, y2, l2);
}

// Kernel B: level 2 -> levels 3..8 in one kernel.
// Block = 64x64 L2 tile (one L8 texel). Grid: 16x16 blocks of 256 threads.
__global__ __launch_bounds__(256) void vt_downB() {
    __shared__ float4 s4[256];   // L4 tile 16x16
    __shared__ float4 s5[64];    // L5 tile 8x8
    __shared__ float4 s6[16];    // L6 tile 4x4
    __shared__ float4 s7[4];     // L7 tile 2x2

    const uint4* __restrict__ L2t = g_mq + OFF_L2;
    unsigned* __restrict__ L3 = reinterpret_cast<unsigned*>(g_mq + OFF_L3);
    unsigned* __restrict__ L4 = reinterpret_cast<unsigned*>(g_mq + OFF_L4);
    unsigned* __restrict__ L5 = reinterpret_cast<unsigned*>(g_mq + OFF_L5);
    unsigned* __restrict__ L6 = reinterpret_cast<unsigned*>(g_mq + OFF_L6);
    unsigned* __restrict__ L7 = reinterpret_cast<unsigned*>(g_mq + OFF_L7);
    unsigned* __restrict__ L8 = reinterpret_cast<unsigned*>(g_mq + OFF_L8);

    int t = threadIdx.x;
    int bx = blockIdx.x, by = blockIdx.y;
    int tx = t & 15, ty = t >> 4;

    // Each thread: 4x4 L2 texels = 4 quad entries at even coords.
    // Each quad == one L3 texel footprint.
    {
        int x0 = 64 * bx + 4 * tx;
        int y0 = 64 * by + 4 * ty;
        const uint4* src = L2t + (size_t)y0 * 1024 + x0;

        float3 l3[4];
        l3[0] = quad_avg(src[0]);                       // (x0,   y0)
        l3[1] = quad_avg(src[2]);                       // (x0+2, y0)
        l3[2] = quad_avg(src[(size_t)2 * 1024]);        // (x0,   y0+2)
        l3[3] = quad_avg(src[(size_t)2 * 1024 + 2]);    // (x0+2, y0+2)

        int x3 = 32 * bx + 2 * tx;
        int y3 = 32 * by + 2 * ty;
        store_quad(L3, 512, x3,     y3,     l3[0]);
        store_quad(L3, 512, x3 + 1, y3,     l3[1]);
        store_quad(L3, 512, x3,     y3 + 1, l3[2]);
        store_quad(L3, 512, x3 + 1, y3 + 1, l3[3]);

        float3 l4 = f3avg(l3[0], l3[1], l3[2], l3[3]);
        store_quad(L4, 256, 16 * bx + tx, 16 * by + ty, l4);
        s4[ty * 16 + tx] = make_float4(l4.x, l4.y, l4.z, 0.0f);
    }
    __syncthreads();

    if (t < 64) {
        int x = t & 7, y = t >> 3;
        float4 v = f4avg4(s4[(2 * y) * 16 + 2 * x],     s4[(2 * y) * 16 + 2 * x + 1],
                          s4[(2 * y + 1) * 16 + 2 * x], s4[(2 * y + 1) * 16 + 2 * x + 1]);
        store_quad(L5, 128, 8 * bx + x, 8 * by + y, make_float3(v.x, v.y, v.z));
        s5[y * 8 + x] = v;
    }
    __syncthreads();

    if (t < 16) {
        int x = t & 3, y = t >> 2;
        float4 v = f4avg4(s5[(2 * y) * 8 + 2 * x],     s5[(2 * y) * 8 + 2 * x + 1],
                          s5[(2 * y + 1) * 8 + 2 * x], s5[(2 * y + 1) * 8 + 2 * x + 1]);
        store_quad(L6, 64, 4 * bx + x, 4 * by + y, make_float3(v.x, v.y, v.z));
        s6[y * 4 + x] = v;
    }
    __syncthreads();

    if (t < 4) {
        int x = t & 1, y = t >> 1;
        float4 v = f4avg4(s6[(2 * y) * 4 + 2 * x],     s6[(2 * y) * 4 + 2 * x + 1],
                          s6[(2 * y + 1) * 4 + 2 * x], s6[(2 * y + 1) * 4 + 2 * x + 1]);
        store_quad(L7, 32, 2 * bx + x, 2 * by + y, make_float3(v.x, v.y, v.z));
        s7[y * 2 + x] = v;
    }
    __syncthreads();

    if (t == 0) {
        float4 a = s7[0], b = s7[1], c = s7[2], d = s7[3];
        store_quad(L8, 16, bx, by,
                   make_float3((a.x + b.x + c.x + d.x) * 0.25f,
                               (a.y + b.y + c.y + d.y) * 0.25f,
                               (a.z + b.z + c.z + d.z) * 0.25f));
    }
}

// wrap helpers
__device__ __forceinline__ void wrap_setup(float u, float v, int w,
                                           int& x0, int& y0, int& x1, int& y1,
                                           float& fx, float& fy) {
    float x = u * (float)w - 0.5f;
    float y = v * (float)w - 0.5f;
    float x0f = floorf(x);
    float y0f = floorf(y);
    fx = x - x0f;
    fy = y - y0f;
    x0 = (int)x0f;
    y0 = (int)y0f;
    if (x0 < 0) x0 += w;
    if (y0 < 0) y0 += w;
    x1 = x0 + 1; if (x1 == w) x1 = 0;
    y1 = y0 + 1; if (y1 == w) y1 = 0;
}

// Bilinear fetch (wrap) from quad mip storage: ONE LDG.128 total.
__device__ __forceinline__ void vt_bilinear_q(const uint4* __restrict__ tex, int w,
                                              float u, float v, float rgb[3]) {
    float x = u * (float)w - 0.5f;
    float y = v * (float)w - 0.5f;
    float x0f = floorf(x);
    float y0f = floorf(y);
    float fx = x - x0f;
    float fy = y - y0f;
    int x0 = (int)x0f;
    int y0 = (int)y0f;
    if (x0 < 0) x0 += w;
    if (y0 < 0) y0 += w;

    uint4 e = tex[(size_t)y0 * w + x0];
    float3 t00 = unpack_rgb(e.x), t01 = unpack_rgb(e.y);
    float3 t10 = unpack_rgb(e.z), t11 = unpack_rgb(e.w);

    float w00 = (1.0f - fx) * (1.0f - fy);
    float w01 = fx * (1.0f - fy);
    float w10 = (1.0f - fx) * fy;
    float w11 = fx * fy;

    rgb[0] = t00.x * w00 + t01.x * w01 + t10.x * w10 + t11.x * w11;
    rgb[1] = t00.y * w00 + t01.y * w01 + t10.y * w10 + t11.y * w11;
    rgb[2] = t00.z * w00 + t01.z * w01 + t10.z * w10 + t11.z * w11;
}

// Exact fp32 bilinear on the base texture (level 0). Rare path.
__device__ __forceinline__ void vt_bilinear0(const float* __restrict__ tex,
                                             float u, float v, float rgb[3]) {
    int x0, y0, x1, y1; float fx, fy;
    wrap_setup(u, v, W0, x0, y0, x1, y1, fx, fy);

    const float* p00 = tex + ((size_t)y0 * W0 + x0) * 3;
    const float* p01 = tex + ((size_t)y0 * W0 + x1) * 3;
    const float* p10 = tex + ((size_t)y1 * W0 + x0) * 3;
    const float* p11 = tex + ((size_t)y1 * W0 + x1) * 3;

    float w00 = (1.0f - fx) * (1.0f - fy);
    float w01 = fx * (1.0f - fy);
    float w10 = (1.0f - fx) * fy;
    float w11 = fx * fy;

#pragma unroll
    for (int c = 0; c < 3; c++)
        rgb[c] = p00[c] * w00 + p01[c] * w01 + p10[c] * w10 + p11[c] * w11;
}

// On-the-fly L1 texel (lx,ly) in exact fp32: avg of base 2x2. float2 loads.
__device__ __forceinline__ float3 l1_texel(const float* __restrict__ base,
                                           int lx, int ly) {
    const float2* r0 = reinterpret_cast<const float2*>(
        base + ((size_t)(2 * ly) * W0 + 2 * lx) * 3);
    const float2* r1 = reinterpret_cast<const float2*>(
        base + ((size_t)(2 * ly + 1) * W0 + 2 * lx) * 3);
    float2 a0 = r0[0], a1 = r0[1], a2 = r0[2];
    float2 b0 = r1[0], b1 = r1[1], b2 = r1[2];
    return make_float3((a0.x + a1.y + b0.x + b1.y) * 0.25f,
                       (a0.y + a2.x + b0.y + b2.x) * 0.25f,
                       (a1.x + a2.y + b1.x + b2.y) * 0.25f);
}

// Exact fp32 bilinear at level 1, L1 texels computed on the fly. Rare path.
__device__ __forceinline__ void vt_bilinear_l1(const float* __restrict__ tex,
                                               float u, float v, float rgb[3]) {
    const int w1 = W0 >> 1;   // 2048
    int x0, y0, x1, y1; float fx, fy;
    wrap_setup(u, v, w1, x0, y0, x1, y1, fx, fy);

    float3 t00 = l1_texel(tex, x0, y0);
    float3 t01 = l1_texel(tex, x1, y0);
    float3 t10 = l1_texel(tex, x0, y1);
    float3 t11 = l1_texel(tex, x1, y1);

    float w00 = (1.0f - fx) * (1.0f - fy);
    float w01 = fx * (1.0f - fy);
    float w10 = (1.0f - fx) * fy;
    float w11 = fx * fy;

    rgb[0] = t00.x * w00 + t01.x * w01 + t10.x * w10 + t11.x * w11;
    rgb[1] = t00.y * w00 + t01.y * w01 + t10.y * w10 + t11.y * w11;
    rgb[2] = t00.z * w00 + t01.z * w01 + t10.z * w10 + t11.z * w11;
}

__device__ __forceinline__ void sample_one(const float* __restrict__ data,
                                           float u, float v, float4 d,
                                           float rgb[3]) {
    float dudx = d.x * (float)W0;
    float dvdx = d.y * (float)W0;
    float dudy = d.z * (float)W0;
    float dvdy = d.w * (float)W0;

    float rho2 = fmaxf(dudx * dudx + dvdx * dvdx, dudy * dudy + dvdy * dvdy);
    float lod = 0.5f * __log2f(fmaxf(rho2, 1e-20f));
    lod = fminf(fmaxf(lod, 0.0f), (float)MAXMIP);

    int l0 = (int)lod;
    if (l0 > MAXMIP) l0 = MAXMIP;
    float frac = lod - (float)l0;
    int l1 = (l0 < MAXMIP) ? (l0 + 1) : MAXMIP;

    float a[3], b[3];
    if (l0 >= 2) {
        // common path (~98.7% of pixels): 2 x LDG.128 total
        vt_bilinear_q(g_mq + MIPQ_OFF[l0], W0 >> l0, u, v, a);
        vt_bilinear_q(g_mq + MIPQ_OFF[l1], W0 >> l1, u, v, b);
    } else if (l0 == 1) {
        vt_bilinear_l1(data, u, v, a);
        vt_bilinear_q(g_mq + OFF_L2, W0 >> 2, u, v, b);
    } else {
        vt_bilinear0(data, u, v, a);
        vt_bilinear_l1(data, u, v, b);
    }

    float w0 = 1.0f - frac;
    rgb[0] = a[0] * w0 + b[0] * frac;
    rgb[1] = a[1] * w0 + b[1] * frac;
    rgb[2] = a[2] * w0 + b[2] * frac;
}

// Two pixels per thread: MLP on the gather path, coalesced IO.
__global__ __launch_bounds__(256) void vt_sample(const float* __restrict__ data,
                          const float4* __restrict__ texc2,
                          const float4* __restrict__ deriv,
                          float* __restrict__ out) {
    int p = blockIdx.x * blockDim.x + threadIdx.x;
    const int npairs = OUTW * OUTW / 2;
    if (p >= npairs) return;

    float4 uvs = texc2[p];                 // (u0,v0,u1,v1)
    float4 d0 = deriv[2 * p];
    float4 d1 = deriv[2 * p + 1];

    float r0[3], r1[3];
    sample_one(data, uvs.x, uvs.y, d0, r0);
    sample_one(data, uvs.z, uvs.w, d1, r1);

    float2* o = reinterpret_cast<float2*>(out + (size_t)6 * p);
    o[0] = make_float2(r0[0], r0[1]);
    o[1] = make_float2(r0[2], r1[0]);
    o[2] = make_float2(r1[1], r1[2]);
}

extern "C" void kernel_launch(void* const* d_in, const int* in_sizes, int n_in,
                              void* d_out, int out_size) {
    const float* data  = (const float*)d_in[0];   // [1,4096,4096,3]
    const float4* texc2 = (const float4*)d_in[1]; // [1,1024,1024,2] read as pairs
    const float4* deriv = (const float4*)d_in[2]; // [1,1024,1024,4]
    float* out = (float*)d_out;                   // [1,1024,1024,3]

    (void)in_sizes; (void)n_in; (void)out_size;

    // A: base -> L2
    vt_downA<<<4096, 256>>>(data);
    // B: L2 -> L3..L8
    {
        dim3 grid(16, 16);
        vt_downB<<<grid, 256>>>();
    }
    // Trilinear sample (2 px/thread)
    vt_sample<<<2048, 256>>>(data, texc2, deriv, out);
}